// round 4
// baseline (speedup 1.0000x reference)
#include <cuda_runtime.h>
#include <cstdint>

#define B_SZ 8192
#define D_SZ 1024
#define E_SZ 32
#define A_SZ 128

// gating weights (k_gate -> k_main); pre-converted/permuted tf32 operands
__device__ float    g_weights[B_SZ * E_SZ];
__device__ uint32_t g_xtf32[(size_t)B_SZ * D_SZ];            // 32 MB, perm layout
__device__ uint32_t g_wtf32p[(size_t)E_SZ * A_SZ * D_SZ];    // 16 MB, perm layout

// ===================== helpers =====================
__device__ __forceinline__ uint32_t smem_u32(const void* p) {
    uint32_t a;
    asm("{ .reg .u64 t; cvta.to.shared.u64 t, %1; cvt.u32.u64 %0, t; }" : "=r"(a) : "l"(p));
    return a;
}
__device__ __forceinline__ uint32_t f2tf32(float f) {
    uint32_t u;
    asm("cvt.rna.tf32.f32 %0, %1;" : "=r"(u) : "f"(f));
    return u;
}
__device__ __forceinline__ void cp16(uint32_t dst, const void* src) {
    asm volatile("cp.async.cg.shared.global [%0], [%1], 16;" :: "r"(dst), "l"(src));
}
#define CP_COMMIT() asm volatile("cp.async.commit_group;" ::: "memory")
#define CP_WAIT4()  asm volatile("cp.async.wait_group 4;" ::: "memory")

// D = A*B + C (accumulate into c)
__device__ __forceinline__ void mma8(float* c, const uint32_t* a, uint32_t b0, uint32_t b1) {
    asm volatile(
        "mma.sync.aligned.m16n8k8.row.col.f32.tf32.tf32.f32 "
        "{%0,%1,%2,%3}, {%4,%5,%6,%7}, {%8,%9}, {%0,%1,%2,%3};"
        : "+f"(c[0]), "+f"(c[1]), "+f"(c[2]), "+f"(c[3])
        : "r"(a[0]), "r"(a[1]), "r"(a[2]), "r"(a[3]), "r"(b0), "r"(b1));
}
// D = A*B + 0 (fresh partial, no separate zeroing)
__device__ __forceinline__ void mma8z(float* c, const uint32_t* a, uint32_t b0, uint32_t b1) {
    asm volatile(
        "mma.sync.aligned.m16n8k8.row.col.f32.tf32.tf32.f32 "
        "{%0,%1,%2,%3}, {%4,%5,%6,%7}, {%8,%9}, {%10,%10,%10,%10};"
        : "=f"(c[0]), "=f"(c[1]), "=f"(c[2]), "=f"(c[3])
        : "r"(a[0]), "r"(a[1]), "r"(a[2]), "r"(a[3]), "r"(b0), "r"(b1), "f"(0.0f));
}

// =====================================================================
// Prepass A: x -> tf32, fragment-permuted.
// Perm within each (b, dc) 32-value chunk: pos qc*8+j holds col 4j+qc.
// Thread i handles (b, dc) = (i>>5, i&31); src chunk = x + i*32 (contig).
// =====================================================================
__global__ __launch_bounds__(256) void convert_x_kernel(const float* __restrict__ x)
{
    size_t i = (size_t)blockIdx.x * 256 + threadIdx.x;   // 0 .. B*32-1
    const float4* src = (const float4*)x + i * 8;
    float4 f[8];
    #pragma unroll
    for (int m = 0; m < 8; m++) f[m] = src[m];
    uint4 o[8];
    #pragma unroll
    for (int qc = 0; qc < 4; qc++) {
        o[2 * qc].x     = f2tf32(((const float*)&f[0])[qc]);
        o[2 * qc].y     = f2tf32(((const float*)&f[1])[qc]);
        o[2 * qc].z     = f2tf32(((const float*)&f[2])[qc]);
        o[2 * qc].w     = f2tf32(((const float*)&f[3])[qc]);
        o[2 * qc + 1].x = f2tf32(((const float*)&f[4])[qc]);
        o[2 * qc + 1].y = f2tf32(((const float*)&f[5])[qc]);
        o[2 * qc + 1].z = f2tf32(((const float*)&f[6])[qc]);
        o[2 * qc + 1].w = f2tf32(((const float*)&f[7])[qc]);
    }
    uint4* dst = (uint4*)g_xtf32 + i * 8;
    #pragma unroll
    for (int m = 0; m < 8; m++) dst[m] = o[m];
}

// =====================================================================
// Prepass B: W_strat -> tf32, fragment-permuted AND (dc,a)-transposed:
// wp[((e*32+dc)*128 + a)*32 + qc*8+j] = W[e][a][dc*32 + 4j+qc]
// Thread i = (e*128+a)*32 + dc; src = W + i*32 (contig).
// =====================================================================
__global__ __launch_bounds__(256) void convert_w_kernel(const float* __restrict__ W)
{
    size_t i = (size_t)blockIdx.x * 256 + threadIdx.x;   // 0 .. E*A*32-1
    int e  = (int)(i >> 12);
    int a  = (int)((i >> 5) & 127);
    int dc = (int)(i & 31);
    const float4* src = (const float4*)W + i * 8;
    float4 f[8];
    #pragma unroll
    for (int m = 0; m < 8; m++) f[m] = src[m];
    uint4 o[8];
    #pragma unroll
    for (int qc = 0; qc < 4; qc++) {
        o[2 * qc].x     = f2tf32(((const float*)&f[0])[qc]);
        o[2 * qc].y     = f2tf32(((const float*)&f[1])[qc]);
        o[2 * qc].z     = f2tf32(((const float*)&f[2])[qc]);
        o[2 * qc].w     = f2tf32(((const float*)&f[3])[qc]);
        o[2 * qc + 1].x = f2tf32(((const float*)&f[4])[qc]);
        o[2 * qc + 1].y = f2tf32(((const float*)&f[5])[qc]);
        o[2 * qc + 1].z = f2tf32(((const float*)&f[6])[qc]);
        o[2 * qc + 1].w = f2tf32(((const float*)&f[7])[qc]);
    }
    uint4* dst = (uint4*)g_wtf32p + ((size_t)(e * 32 + dc) * 128 + a) * 8;
    #pragma unroll
    for (int m = 0; m < 8; m++) dst[m] = o[m];
}

// =====================================================================
// Kernel: gating (R1, known-correct). Seeds out with the b_strat bias term.
// =====================================================================
__global__ __launch_bounds__(128) void gating_kernel(
    const float* __restrict__ x, const float* __restrict__ W_att,
    const float* __restrict__ b_att, const float* __restrict__ abias,
    const float* __restrict__ b_strat, const float* __restrict__ gu,
    float* __restrict__ out)
{
    __shared__ float xs[32][64];
    __shared__ float was[32][32];
    __shared__ float L[64][33];
    __shared__ float Wg[64][33];

    const int tid = threadIdx.x;
    const int b0 = blockIdx.x * 64;
    const int tb = tid & 15;
    const int te = tid >> 4;

    float acc[4][4] = {};

    for (int d0 = 0; d0 < D_SZ; d0 += 32) {
        #pragma unroll
        for (int i = 0; i < 4; i++) {
            int f = tid + i * 128;
            int row = f >> 3, c4 = f & 7;
            float4 v = *(const float4*)&x[(size_t)(b0 + row) * D_SZ + d0 + c4 * 4];
            xs[c4 * 4 + 0][row] = v.x; xs[c4 * 4 + 1][row] = v.y;
            xs[c4 * 4 + 2][row] = v.z; xs[c4 * 4 + 3][row] = v.w;
        }
        #pragma unroll
        for (int i = 0; i < 2; i++) {
            int f = tid + i * 128;
            int row = f >> 3, c4 = f & 7;
            float4 v = *(const float4*)&W_att[(size_t)row * D_SZ + d0 + c4 * 4];
            was[c4 * 4 + 0][row] = v.x; was[c4 * 4 + 1][row] = v.y;
            was[c4 * 4 + 2][row] = v.z; was[c4 * 4 + 3][row] = v.w;
        }
        __syncthreads();
        #pragma unroll 8
        for (int kk = 0; kk < 32; kk++) {
            float4 av = *(const float4*)&xs[kk][tb * 4];
            float4 ev = *(const float4*)&was[kk][te * 4];
            float a_[4] = {av.x, av.y, av.z, av.w};
            float e_[4] = {ev.x, ev.y, ev.z, ev.w};
            #pragma unroll
            for (int i = 0; i < 4; i++)
                #pragma unroll
                for (int j = 0; j < 4; j++)
                    acc[i][j] = fmaf(a_[i], e_[j], acc[i][j]);
        }
        __syncthreads();
    }

    #pragma unroll
    for (int i = 0; i < 4; i++)
        #pragma unroll
        for (int j = 0; j < 4; j++)
            L[tb * 4 + i][te * 4 + j] = acc[i][j];
    __syncthreads();

    if (tid < 64) {
        int b = b0 + tid;
        float v[E_SZ];
        float mx = -1e30f;
        #pragma unroll
        for (int e = 0; e < E_SZ; e++) {
            float u = gu[(size_t)b * E_SZ + e];
            float g = -logf(-logf(u + 1e-10f) + 1e-10f);
            float t = L[tid][e] + b_att[e] + abias[e] + g;   // TAU = 1.0
            v[e] = t;
            mx = fmaxf(mx, t);
        }
        float s = 0.f;
        #pragma unroll
        for (int e = 0; e < E_SZ; e++) { v[e] = expf(v[e] - mx); s += v[e]; }
        float inv = 1.f / s;
        #pragma unroll
        for (int e = 0; e < E_SZ; e++) {
            float w = v[e] * inv;
            Wg[tid][e] = w;
            g_weights[(size_t)b * E_SZ + e] = w;
        }
    }
    __syncthreads();

    for (int idx = tid; idx < 64 * A_SZ; idx += 128) {
        int r = idx >> 7, a = idx & 127;
        float s = 0.f;
        #pragma unroll
        for (int e = 0; e < E_SZ; e++)
            s = fmaf(Wg[r][e], b_strat[e * A_SZ + a], s);
        out[(size_t)(b0 + r) * A_SZ + a] = s;
    }
}

// =====================================================================
// Main: per (expert, d-chunk) partial tile via zero-C mma, fp32 FMA merge
// with gating weight. CTA 128x64, 8 warps as 2M x 4N (warp tile 64x16).
// A frags cached in regs across the 32-expert inner loop. W ring-6
// cp.async, wait_group 4; x double-buffered; one barrier per tile.
// =====================================================================
#define NTT   1024                      // 32 dc * 32 e
#define XSTG  18432                     // 128 rows * 144B
#define WSTG  9216                      // 64 rows * 144B
#define XOFF  16384                     // after w_s (32*64 float2)
#define WOFF  (XOFF + 2 * XSTG)         // 53248
#define SMEM_TOT (WOFF + 6 * WSTG)      // 108544

__global__ __launch_bounds__(256, 1) void main_kernel(float* __restrict__ out)
{
    extern __shared__ char smem[];
    float2* w_s = (float2*)smem;        // [e][64] row-pairs, warp-layout order
    const uint32_t sb = smem_u32(smem);
    const int tid = threadIdx.x;
    const int lane = tid & 31, wid = tid >> 5;
    const int warpM = wid >> 2, warpN = wid & 3;     // 2M x 4N
    const int g = lane >> 2, qc = lane & 3;
    const int b0 = blockIdx.x * 128;
    const int a0 = blockIdx.y * 64;

    // gating weights, pre-paired for LDS.64: pair p -> rows (row(p), row(p)+8)
    for (int i = tid; i < E_SZ * 64; i += 256) {
        int e = i >> 6, p = i & 63;
        int row = (p >> 5) * 64 + ((p >> 3) & 3) * 16 + (p & 7);
        float2 w2;
        w2.x = g_weights[(size_t)(b0 + row) * E_SZ + e];
        w2.y = g_weights[(size_t)(b0 + row + 8) * E_SZ + e];
        w_s[i] = w2;
    }

    auto cp_x = [&](int dc) {
        uint32_t base = sb + XOFF + (dc & 1) * XSTG;
        const char* src = (const char*)g_xtf32 + ((size_t)b0 * 32 + dc) * 128;
        #pragma unroll
        for (int j = 0; j < 4; j++) {
            int f = tid + j * 256;                   // 0..1023
            int row = f >> 3, c = f & 7;
            cp16(base + row * 144 + c * 16, src + (size_t)row * 4096 + c * 16);
        }
    };
    auto cp_w = [&](int t, int stage) {
        int dc = t >> 5, e = t & 31;
        uint32_t base = sb + WOFF + stage * WSTG;
        const char* src = (const char*)g_wtf32p +
                          ((size_t)(e * 32 + dc) * 128 + a0) * 128;
        #pragma unroll
        for (int j = 0; j < 2; j++) {
            int f = tid + j * 256;                   // 0..511
            int ar = f >> 3, c = f & 7;
            cp16(base + ar * 144 + c * 16, src + (size_t)ar * 128 + c * 16);
        }
    };

    // prologue: groups for virtual iters -4..-1
    cp_x(0); cp_w(0, 0); CP_COMMIT();
    cp_w(1, 1); CP_COMMIT();
    cp_w(2, 2); CP_COMMIT();
    cp_w(3, 3); CP_COMMIT();

    uint32_t a_[4][4][4];                            // [ks][mt][i], cached per dc
    float master[4][2][4] = {};
    int st_pf = 4, st_rd = 0;

    for (int t = 0; t < NTT; t++) {
        const int dc = t >> 5, e = t & 31;
        if (t + 4 < NTT) cp_w(t + 4, st_pf);
        if (++st_pf == 6) st_pf = 0;
        if (e == 28 && dc < 31) cp_x(dc + 1);
        CP_COMMIT();
        CP_WAIT4();
        __syncthreads();

        if (e == 0) {
            const char* xb = smem + XOFF + (dc & 1) * XSTG;
            #pragma unroll
            for (int mt = 0; mt < 4; mt++) {
                int r0 = warpM * 64 + mt * 16 + g;
                uint4 v0 = *(const uint4*)(xb + r0 * 144 + qc * 32);
                uint4 v1 = *(const uint4*)(xb + r0 * 144 + qc * 32 + 16);
                uint4 v2 = *(const uint4*)(xb + (r0 + 8) * 144 + qc * 32);
                uint4 v3 = *(const uint4*)(xb + (r0 + 8) * 144 + qc * 32 + 16);
                a_[0][mt][0] = v0.x; a_[0][mt][2] = v0.y;
                a_[1][mt][0] = v0.z; a_[1][mt][2] = v0.w;
                a_[2][mt][0] = v1.x; a_[2][mt][2] = v1.y;
                a_[3][mt][0] = v1.z; a_[3][mt][2] = v1.w;
                a_[0][mt][1] = v2.x; a_[0][mt][3] = v2.y;
                a_[1][mt][1] = v2.z; a_[1][mt][3] = v2.w;
                a_[2][mt][1] = v3.x; a_[2][mt][3] = v3.y;
                a_[3][mt][1] = v3.z; a_[3][mt][3] = v3.w;
            }
        }

        // B fragments (2 LDS.128 per nt)
        const char* wb = smem + WOFF + st_rd * WSTG;
        if (++st_rd == 6) st_rd = 0;
        uint32_t bfr[2][4][2];
        #pragma unroll
        for (int nt = 0; nt < 2; nt++) {
            int ar = warpN * 16 + nt * 8 + g;
            uint4 lo = *(const uint4*)(wb + ar * 144 + qc * 32);
            uint4 hi = *(const uint4*)(wb + ar * 144 + qc * 32 + 16);
            bfr[nt][0][0] = lo.x; bfr[nt][0][1] = lo.y;
            bfr[nt][1][0] = lo.z; bfr[nt][1][1] = lo.w;
            bfr[nt][2][0] = hi.x; bfr[nt][2][1] = hi.y;
            bfr[nt][3][0] = hi.z; bfr[nt][3][1] = hi.w;
        }

        // partial = A * B  (zero-C first ks, then accumulate)
        float part[4][2][4];
        #pragma unroll
        for (int mt = 0; mt < 4; mt++)
            #pragma unroll
            for (int nt = 0; nt < 2; nt++)
                mma8z(part[mt][nt], a_[0][mt], bfr[nt][0][0], bfr[nt][0][1]);
        #pragma unroll
        for (int ks = 1; ks < 4; ks++)
            #pragma unroll
            for (int mt = 0; mt < 4; mt++)
                #pragma unroll
                for (int nt = 0; nt < 2; nt++)
                    mma8(part[mt][nt], a_[ks][mt], bfr[nt][ks][0], bfr[nt][ks][1]);

        // master += w * partial  (exact fp32 weighted merge)
        #pragma unroll
        for (int mt = 0; mt < 4; mt++) {
            float2 wv = w_s[e * 64 + warpM * 32 + mt * 8 + g];
            #pragma unroll
            for (int nt = 0; nt < 2; nt++) {
                master[mt][nt][0] = fmaf(wv.x, part[mt][nt][0], master[mt][nt][0]);
                master[mt][nt][1] = fmaf(wv.x, part[mt][nt][1], master[mt][nt][1]);
                master[mt][nt][2] = fmaf(wv.y, part[mt][nt][2], master[mt][nt][2]);
                master[mt][nt][3] = fmaf(wv.y, part[mt][nt][3], master[mt][nt][3]);
            }
        }
    }

    // epilogue: accumulate onto bias term already in out
    #pragma unroll
    for (int mt = 0; mt < 4; mt++) {
        int r = b0 + warpM * 64 + mt * 16 + g;
        #pragma unroll
        for (int nt = 0; nt < 2; nt++) {
            int c = a0 + warpN * 16 + nt * 8 + qc * 2;
            float2* p0 = (float2*)&out[(size_t)r * A_SZ + c];
            float2 v0 = *p0;
            v0.x += master[mt][nt][0]; v0.y += master[mt][nt][1];
            *p0 = v0;
            float2* p1 = (float2*)&out[(size_t)(r + 8) * A_SZ + c];
            float2 v1 = *p1;
            v1.x += master[mt][nt][2]; v1.y += master[mt][nt][3];
            *p1 = v1;
        }
    }
}

// =====================================================================
extern "C" void kernel_launch(void* const* d_in, const int* in_sizes, int n_in,
                              void* d_out, int out_size) {
    const float* x       = (const float*)d_in[0];
    const float* W_att   = (const float*)d_in[1];
    const float* b_att   = (const float*)d_in[2];
    const float* abias   = (const float*)d_in[3];
    const float* W_strat = (const float*)d_in[4];
    const float* b_strat = (const float*)d_in[5];
    const float* gu      = (const float*)d_in[6];
    float* out = (float*)d_out;

    cudaFuncSetAttribute(main_kernel, cudaFuncAttributeMaxDynamicSharedMemorySize,
                         SMEM_TOT);

    convert_x_kernel<<<(B_SZ * 32) / 256, 256>>>(x);
    convert_w_kernel<<<(E_SZ * A_SZ * 32) / 256, 256>>>(W_strat);
    gating_kernel<<<B_SZ / 64, 128>>>(x, W_att, b_att, abias, b_strat, gu, out);
    main_kernel<<<dim3(B_SZ / 128, A_SZ / 64), 256, SMEM_TOT>>>(out);
}

// round 7
// speedup vs baseline: 2.0147x; 2.0147x over previous
#include <cuda_runtime.h>
#include <cuda_fp16.h>
#include <cstdint>

#define B_SZ 8192
#define D_SZ 1024
#define E_SZ 32
#define A_SZ 128

// gating weights; fragment-ordered fp16 operands
__device__ float g_weights[B_SZ * E_SZ];
__device__ uint4 g_xh[(size_t)B_SZ * D_SZ / 8];              // 16 MB (8 halves/uint4)
__device__ uint4 g_wh[(size_t)E_SZ * A_SZ * D_SZ / 8];       // 8 MB  (8 halves/uint4)

// ===================== helpers =====================
__device__ __forceinline__ uint32_t smem_u32(const void* p) {
    uint32_t a;
    asm("{ .reg .u64 t; cvta.to.shared.u64 t, %1; cvt.u32.u64 %0, t; }" : "=r"(a) : "l"(p));
    return a;
}
__device__ __forceinline__ uint32_t pk(float a, float b) {
    __half2 h = __floats2half2_rn(a, b);
    return *(uint32_t*)&h;
}
__device__ __forceinline__ void cp16(uint32_t dst, const void* src) {
    asm volatile("cp.async.cg.shared.global [%0], [%1], 16;" :: "r"(dst), "l"(src));
}
#define CP_COMMIT() asm volatile("cp.async.commit_group;" ::: "memory")
#define CP_WAIT2()  asm volatile("cp.async.wait_group 2;" ::: "memory")

// fp16 m16n8k16: D(f32) = A*B + C
__device__ __forceinline__ void mma16(float* c, const uint4& a, uint32_t b0, uint32_t b1) {
    asm volatile(
        "mma.sync.aligned.m16n8k16.row.col.f32.f16.f16.f32 "
        "{%0,%1,%2,%3}, {%4,%5,%6,%7}, {%8,%9}, {%0,%1,%2,%3};"
        : "+f"(c[0]), "+f"(c[1]), "+f"(c[2]), "+f"(c[3])
        : "r"(a.x), "r"(a.y), "r"(a.z), "r"(a.w), "r"(b0), "r"(b1));
}
__device__ __forceinline__ void mma16z(float* c, const uint4& a, uint32_t b0, uint32_t b1) {
    asm volatile(
        "mma.sync.aligned.m16n8k16.row.col.f32.f16.f16.f32 "
        "{%0,%1,%2,%3}, {%4,%5,%6,%7}, {%8,%9}, {%10,%10,%10,%10};"
        : "=f"(c[0]), "=f"(c[1]), "=f"(c[2]), "=f"(c[3])
        : "r"(a.x), "r"(a.y), "r"(a.z), "r"(a.w), "r"(b0), "r"(b1), "f"(0.0f));
}

// =====================================================================
// Prepass A: x -> fp16, fragment-ordered.
// g_xh[(M0*16 + P)*512 + fid*32 + lane] = uint4 A-fragment regs
// fid = (dcsub*2+ks)*4 + mt;  frag covers rows M0*64+mt*16..+15,
// k = P*64 + dcsub*32 + ks*16 .. +15.
// =====================================================================
__global__ __launch_bounds__(256) void convert_x_h(const float* __restrict__ x)
{
    int tid = blockIdx.x * 256 + threadIdx.x;         // 0 .. 1048575
    int lane = tid & 31, fid = (tid >> 5) & 15, P = (tid >> 9) & 15, M0 = tid >> 13;
    int mt = fid & 3, ks = (fid >> 2) & 1, dcsub = fid >> 3;
    int row = M0 * 64 + mt * 16 + (lane >> 2);
    int kb  = P * 64 + dcsub * 32 + ks * 16 + (lane & 3) * 2;
    const float* r0 = x + (size_t)row * D_SZ + kb;
    const float* r1 = r0 + 8 * D_SZ;
    uint4 o;
    o.x = pk(r0[0], r0[1]);      // a0: (row,   k..k+1)
    o.y = pk(r1[0], r1[1]);      // a1: (row+8, k..k+1)
    o.z = pk(r0[8], r0[9]);      // a2: (row,   k+8..k+9)
    o.w = pk(r1[8], r1[9]);      // a3: (row+8, k+8..k+9)
    g_xh[tid] = o;
}

// =====================================================================
// Prepass B: W_strat -> fp16, fragment-ordered.
// g_wh[(((e*16+P)*16 + cb)*2 + dcsub)*32 + lane] =
//   {ks0:b0,b1, ks1:b0,b1} for col a = cb*8 + lane/4.
// Grid covers all 32 experts: (E*A*D/8)/256 = 2048 blocks.
// =====================================================================
__global__ __launch_bounds__(256) void convert_w_h(const float* __restrict__ W)
{
    int tid = blockIdx.x * 256 + threadIdx.x;         // 0 .. 524287
    int lane = tid & 31, dcsub = (tid >> 5) & 1, cb = (tid >> 6) & 15;
    int P = (tid >> 10) & 15, e = tid >> 14;          // e = 0..31
    int a  = cb * 8 + (lane >> 2);
    int tg = lane & 3;
    const float* base = W + ((size_t)e * A_SZ + a) * D_SZ + P * 64 + dcsub * 32 + tg * 2;
    uint4 o;
    o.x = pk(base[0],  base[1]);    // ks0 b0: k,k+1
    o.y = pk(base[8],  base[9]);    // ks0 b1: k+8,k+9
    o.z = pk(base[16], base[17]);   // ks1 b0
    o.w = pk(base[24], base[25]);   // ks1 b1
    g_wh[tid] = o;
}

// =====================================================================
// Kernel: gating (R1, known-correct). Seeds out with the b_strat bias term.
// =====================================================================
__global__ __launch_bounds__(128) void gating_kernel(
    const float* __restrict__ x, const float* __restrict__ W_att,
    const float* __restrict__ b_att, const float* __restrict__ abias,
    const float* __restrict__ b_strat, const float* __restrict__ gu,
    float* __restrict__ out)
{
    __shared__ float xs[32][64];
    __shared__ float was[32][32];
    __shared__ float L[64][33];
    __shared__ float Wg[64][33];

    const int tid = threadIdx.x;
    const int b0 = blockIdx.x * 64;
    const int tb = tid & 15;
    const int te = tid >> 4;

    float acc[4][4] = {};

    for (int d0 = 0; d0 < D_SZ; d0 += 32) {
        #pragma unroll
        for (int i = 0; i < 4; i++) {
            int f = tid + i * 128;
            int row = f >> 3, c4 = f & 7;
            float4 v = *(const float4*)&x[(size_t)(b0 + row) * D_SZ + d0 + c4 * 4];
            xs[c4 * 4 + 0][row] = v.x; xs[c4 * 4 + 1][row] = v.y;
            xs[c4 * 4 + 2][row] = v.z; xs[c4 * 4 + 3][row] = v.w;
        }
        #pragma unroll
        for (int i = 0; i < 2; i++) {
            int f = tid + i * 128;
            int row = f >> 3, c4 = f & 7;
            float4 v = *(const float4*)&W_att[(size_t)row * D_SZ + d0 + c4 * 4];
            was[c4 * 4 + 0][row] = v.x; was[c4 * 4 + 1][row] = v.y;
            was[c4 * 4 + 2][row] = v.z; was[c4 * 4 + 3][row] = v.w;
        }
        __syncthreads();
        #pragma unroll 8
        for (int kk = 0; kk < 32; kk++) {
            float4 av = *(const float4*)&xs[kk][tb * 4];
            float4 ev = *(const float4*)&was[kk][te * 4];
            float a_[4] = {av.x, av.y, av.z, av.w};
            float e_[4] = {ev.x, ev.y, ev.z, ev.w};
            #pragma unroll
            for (int i = 0; i < 4; i++)
                #pragma unroll
                for (int j = 0; j < 4; j++)
                    acc[i][j] = fmaf(a_[i], e_[j], acc[i][j]);
        }
        __syncthreads();
    }

    #pragma unroll
    for (int i = 0; i < 4; i++)
        #pragma unroll
        for (int j = 0; j < 4; j++)
            L[tb * 4 + i][te * 4 + j] = acc[i][j];
    __syncthreads();

    if (tid < 64) {
        int b = b0 + tid;
        float v[E_SZ];
        float mx = -1e30f;
        #pragma unroll
        for (int e = 0; e < E_SZ; e++) {
            float u = gu[(size_t)b * E_SZ + e];
            float g = -logf(-logf(u + 1e-10f) + 1e-10f);
            float t = L[tid][e] + b_att[e] + abias[e] + g;   // TAU = 1.0
            v[e] = t;
            mx = fmaxf(mx, t);
        }
        float s = 0.f;
        #pragma unroll
        for (int e = 0; e < E_SZ; e++) { v[e] = expf(v[e] - mx); s += v[e]; }
        float inv = 1.f / s;
        #pragma unroll
        for (int e = 0; e < E_SZ; e++) {
            float w = v[e] * inv;
            Wg[tid][e] = w;
            g_weights[(size_t)b * E_SZ + e] = w;
        }
    }
    __syncthreads();

    for (int idx = tid; idx < 64 * A_SZ; idx += 128) {
        int r = idx >> 7, a = idx & 127;
        float s = 0.f;
        #pragma unroll
        for (int e = 0; e < E_SZ; e++)
            s = fmaf(Wg[r][e], b_strat[e * A_SZ + a], s);
        out[(size_t)(b0 + r) * A_SZ + a] = s;
    }
}

// =====================================================================
// Main: fp16 m16n8k16. CTA 128x64, 512 threads, 16 warps as 2M x 8N
// (warp tile 64x8). Per (e, 64k-chunk): partial over 4 HMMA, then fp32
// weighted merge. A frags cached in regs per chunk. W ring-4 cp.async
// (distance 2), x double-buffered, one barrier per iter.
// =====================================================================
#define NTT   512                        // 16 P-chunks * 32 experts
#define WSB   16384                      // w_s: 32 e * 64 float2
#define XOFF  WSB
#define XBUF  16384                      // 2 mblocks * 8KB
#define WOFF  (XOFF + 2 * XBUF)          // 49152
#define WSTG  8192
#define SMEM_TOT (WOFF + 4 * WSTG)       // 81920

__global__ __launch_bounds__(512, 1) void main_kernel(float* __restrict__ out)
{
    extern __shared__ char smem[];
    float2* w_s = (float2*)smem;         // [e][64] row-pairs
    const uint32_t sb = smem_u32(smem);
    const int tid = threadIdx.x;
    const int lane = tid & 31, wid = tid >> 5;
    const int wm = wid >> 3, wn = wid & 7;        // 2M x 8N
    const int g = lane >> 2, tg = lane & 3;
    const int b0 = blockIdx.x * 128;
    const int a0 = blockIdx.y * 64;

    // gating weights, pre-paired: pair p=(wm,mt,g) -> rows (row, row+8)
    for (int i = tid; i < E_SZ * 64; i += 512) {
        int e = i >> 6, p = i & 63;
        int row = (p >> 5) * 64 + ((p >> 3) & 3) * 16 + (p & 7);
        float2 w2;
        w2.x = g_weights[(size_t)(b0 + row) * E_SZ + e];
        w2.y = g_weights[(size_t)(b0 + row + 8) * E_SZ + e];
        w_s[i] = w2;
    }

    auto cp_x = [&](int P) {
        uint32_t base = sb + XOFF + (P & 1) * XBUF;
        #pragma unroll
        for (int j = 0; j < 2; j++) {
            int f = tid + j * 512;                // 0..1023 16B-units
            int mb = f >> 9, rem = f & 511;
            const char* src = (const char*)g_xh +
                              ((size_t)((blockIdx.x * 2 + mb) * 16 + P)) * 8192 + rem * 16;
            cp16(base + f * 16, src);
        }
    };
    auto cp_w = [&](int t) {
        int P = t >> 5, e = t & 31;
        const char* src = (const char*)g_wh +
                          ((size_t)((e * 16 + P) * 16 + blockIdx.y * 8)) * 1024 + tid * 16;
        cp16(sb + WOFF + (t & 3) * WSTG + tid * 16, src);
    };

    // prologue: groups G0={x0,w0}, G1={w1}
    cp_x(0); cp_w(0); CP_COMMIT();
    cp_w(1); CP_COMMIT();

    uint4 a_[2][2][4];                   // [dcsub][ks][mt]
    float master[4][4] = {};

    for (int t = 0; t < NTT; t++) {
        const int P = t >> 5, e = t & 31;
        if (t + 2 < NTT) cp_w(t + 2);
        if (e == 28 && P < 15) cp_x(P + 1);
        CP_COMMIT();
        CP_WAIT2();
        __syncthreads();

        if (e == 0) {
            const char* xb = smem + XOFF + (P & 1) * XBUF + wm * 8192;
            #pragma unroll
            for (int dcsub = 0; dcsub < 2; dcsub++)
                #pragma unroll
                for (int ks = 0; ks < 2; ks++)
                    #pragma unroll
                    for (int mt = 0; mt < 4; mt++) {
                        int fid = (dcsub * 2 + ks) * 4 + mt;
                        a_[dcsub][ks][mt] =
                            *(const uint4*)(xb + fid * 512 + lane * 16);
                    }
        }

        const char* wb = smem + WOFF + (t & 3) * WSTG + wn * 1024;
        uint4 bfr0 = *(const uint4*)(wb + lane * 16);
        uint4 bfr1 = *(const uint4*)(wb + 512 + lane * 16);

        #pragma unroll
        for (int mt = 0; mt < 4; mt++) {
            float part[4];
            mma16z(part, a_[0][0][mt], bfr0.x, bfr0.y);
            mma16 (part, a_[0][1][mt], bfr0.z, bfr0.w);
            mma16 (part, a_[1][0][mt], bfr1.x, bfr1.y);
            mma16 (part, a_[1][1][mt], bfr1.z, bfr1.w);
            float2 w2 = w_s[e * 64 + wm * 32 + mt * 8 + g];
            master[mt][0] = fmaf(w2.x, part[0], master[mt][0]);
            master[mt][1] = fmaf(w2.x, part[1], master[mt][1]);
            master[mt][2] = fmaf(w2.y, part[2], master[mt][2]);
            master[mt][3] = fmaf(w2.y, part[3], master[mt][3]);
        }
    }

    // epilogue: accumulate onto bias term already in out
    #pragma unroll
    for (int mt = 0; mt < 4; mt++) {
        int r = b0 + wm * 64 + mt * 16 + g;
        int c = a0 + wn * 8 + tg * 2;
        float2* p0 = (float2*)&out[(size_t)r * A_SZ + c];
        float2 v0 = *p0;
        v0.x += master[mt][0]; v0.y += master[mt][1];
        *p0 = v0;
        float2* p1 = (float2*)&out[(size_t)(r + 8) * A_SZ + c];
        float2 v1 = *p1;
        v1.x += master[mt][2]; v1.y += master[mt][3];
        *p1 = v1;
    }
}

// =====================================================================
extern "C" void kernel_launch(void* const* d_in, const int* in_sizes, int n_in,
                              void* d_out, int out_size) {
    const float* x       = (const float*)d_in[0];
    const float* W_att   = (const float*)d_in[1];
    const float* b_att   = (const float*)d_in[2];
    const float* abias   = (const float*)d_in[3];
    const float* W_strat = (const float*)d_in[4];
    const float* b_strat = (const float*)d_in[5];
    const float* gu      = (const float*)d_in[6];
    float* out = (float*)d_out;

    cudaFuncSetAttribute(main_kernel, cudaFuncAttributeMaxDynamicSharedMemorySize,
                         SMEM_TOT);

    convert_x_h<<<(B_SZ * D_SZ / 8) / 256, 256>>>(x);
    convert_w_h<<<(E_SZ * A_SZ * D_SZ / 8) / 256, 256>>>(W_strat);
    gating_kernel<<<B_SZ / 64, 128>>>(x, W_att, b_att, abias, b_strat, gu, out);
    main_kernel<<<dim3(B_SZ / 128, A_SZ / 64), 512, SMEM_TOT>>>(out);
}

// round 9
// speedup vs baseline: 2.1799x; 1.0820x over previous
#include <cuda_runtime.h>
#include <cuda_fp16.h>
#include <cstdint>

#define B_SZ 8192
#define D_SZ 1024
#define E_SZ 32
#define A_SZ 128

// gating weights; fragment-ordered fp16 operands
__device__ float g_weights[B_SZ * E_SZ];
__device__ uint4 g_xh[(size_t)B_SZ * D_SZ / 8];              // 16 MB (8 halves/uint4)
__device__ uint4 g_wh[(size_t)E_SZ * A_SZ * D_SZ / 8];       // 8 MB  (8 halves/uint4)

// ===================== helpers =====================
__device__ __forceinline__ uint32_t smem_u32(const void* p) {
    uint32_t a;
    asm("{ .reg .u64 t; cvta.to.shared.u64 t, %1; cvt.u32.u64 %0, t; }" : "=r"(a) : "l"(p));
    return a;
}
__device__ __forceinline__ uint32_t pk(float a, float b) {
    __half2 h = __floats2half2_rn(a, b);
    return *(uint32_t*)&h;
}
__device__ __forceinline__ void cp16(uint32_t dst, const void* src) {
    asm volatile("cp.async.cg.shared.global [%0], [%1], 16;" :: "r"(dst), "l"(src));
}
#define CP_COMMIT() asm volatile("cp.async.commit_group;" ::: "memory")
#define CP_WAIT4()  asm volatile("cp.async.wait_group 4;" ::: "memory")

// fp16 m16n8k16: D(f32) = A*B + C
__device__ __forceinline__ void mma16(float* c, const uint4& a, uint32_t b0, uint32_t b1) {
    asm volatile(
        "mma.sync.aligned.m16n8k16.row.col.f32.f16.f16.f32 "
        "{%0,%1,%2,%3}, {%4,%5,%6,%7}, {%8,%9}, {%0,%1,%2,%3};"
        : "+f"(c[0]), "+f"(c[1]), "+f"(c[2]), "+f"(c[3])
        : "r"(a.x), "r"(a.y), "r"(a.z), "r"(a.w), "r"(b0), "r"(b1));
}
__device__ __forceinline__ void mma16z(float* c, const uint4& a, uint32_t b0, uint32_t b1) {
    asm volatile(
        "mma.sync.aligned.m16n8k16.row.col.f32.f16.f16.f32 "
        "{%0,%1,%2,%3}, {%4,%5,%6,%7}, {%8,%9}, {%10,%10,%10,%10};"
        : "=f"(c[0]), "=f"(c[1]), "=f"(c[2]), "=f"(c[3])
        : "r"(a.x), "r"(a.y), "r"(a.z), "r"(a.w), "r"(b0), "r"(b1), "f"(0.0f));
}

// =====================================================================
// Prepass A: x -> fp16, fragment-ordered.
// g_xh[(M0*16 + P)*512 + fid*32 + lane] = uint4 A-fragment regs
// fid = (dcsub*2+ks)*4 + mt;  frag covers rows M0*64+mt*16..+15,
// k = P*64 + dcsub*32 + ks*16 .. +15.
// =====================================================================
__global__ __launch_bounds__(256) void convert_x_h(const float* __restrict__ x)
{
    int tid = blockIdx.x * 256 + threadIdx.x;         // 0 .. 1048575
    int lane = tid & 31, fid = (tid >> 5) & 15, P = (tid >> 9) & 15, M0 = tid >> 13;
    int mt = fid & 3, ks = (fid >> 2) & 1, dcsub = fid >> 3;
    int row = M0 * 64 + mt * 16 + (lane >> 2);
    int kb  = P * 64 + dcsub * 32 + ks * 16 + (lane & 3) * 2;
    const float* r0 = x + (size_t)row * D_SZ + kb;
    const float* r1 = r0 + 8 * D_SZ;
    uint4 o;
    o.x = pk(r0[0], r0[1]);      // a0: (row,   k..k+1)
    o.y = pk(r1[0], r1[1]);      // a1: (row+8, k..k+1)
    o.z = pk(r0[8], r0[9]);      // a2: (row,   k+8..k+9)
    o.w = pk(r1[8], r1[9]);      // a3: (row+8, k+8..k+9)
    g_xh[tid] = o;
}

// =====================================================================
// Prepass B: W_strat -> fp16, fragment-ordered.
// g_wh[(((e*16+P)*16 + cb)*2 + dcsub)*32 + lane] =
//   {ks0:b0,b1, ks1:b0,b1} for col a = cb*8 + lane/4.
// =====================================================================
__global__ __launch_bounds__(256) void convert_w_h(const float* __restrict__ W)
{
    int tid = blockIdx.x * 256 + threadIdx.x;         // 0 .. 524287
    int lane = tid & 31, dcsub = (tid >> 5) & 1, cb = (tid >> 6) & 15;
    int P = (tid >> 10) & 15, e = tid >> 14;          // e = 0..31
    int a  = cb * 8 + (lane >> 2);
    int tg = lane & 3;
    const float* base = W + ((size_t)e * A_SZ + a) * D_SZ + P * 64 + dcsub * 32 + tg * 2;
    uint4 o;
    o.x = pk(base[0],  base[1]);    // ks0 b0: k,k+1
    o.y = pk(base[8],  base[9]);    // ks0 b1: k+8,k+9
    o.z = pk(base[16], base[17]);   // ks1 b0
    o.w = pk(base[24], base[25]);   // ks1 b1
    g_wh[tid] = o;
}

// =====================================================================
// Kernel: gating (R1, known-correct). Seeds out with the b_strat bias term.
// =====================================================================
__global__ __launch_bounds__(128) void gating_kernel(
    const float* __restrict__ x, const float* __restrict__ W_att,
    const float* __restrict__ b_att, const float* __restrict__ abias,
    const float* __restrict__ b_strat, const float* __restrict__ gu,
    float* __restrict__ out)
{
    __shared__ float xs[32][64];
    __shared__ float was[32][32];
    __shared__ float L[64][33];
    __shared__ float Wg[64][33];

    const int tid = threadIdx.x;
    const int b0 = blockIdx.x * 64;
    const int tb = tid & 15;
    const int te = tid >> 4;

    float acc[4][4] = {};

    for (int d0 = 0; d0 < D_SZ; d0 += 32) {
        #pragma unroll
        for (int i = 0; i < 4; i++) {
            int f = tid + i * 128;
            int row = f >> 3, c4 = f & 7;
            float4 v = *(const float4*)&x[(size_t)(b0 + row) * D_SZ + d0 + c4 * 4];
            xs[c4 * 4 + 0][row] = v.x; xs[c4 * 4 + 1][row] = v.y;
            xs[c4 * 4 + 2][row] = v.z; xs[c4 * 4 + 3][row] = v.w;
        }
        #pragma unroll
        for (int i = 0; i < 2; i++) {
            int f = tid + i * 128;
            int row = f >> 3, c4 = f & 7;
            float4 v = *(const float4*)&W_att[(size_t)row * D_SZ + d0 + c4 * 4];
            was[c4 * 4 + 0][row] = v.x; was[c4 * 4 + 1][row] = v.y;
            was[c4 * 4 + 2][row] = v.z; was[c4 * 4 + 3][row] = v.w;
        }
        __syncthreads();
        #pragma unroll 8
        for (int kk = 0; kk < 32; kk++) {
            float4 av = *(const float4*)&xs[kk][tb * 4];
            float4 ev = *(const float4*)&was[kk][te * 4];
            float a_[4] = {av.x, av.y, av.z, av.w};
            float e_[4] = {ev.x, ev.y, ev.z, ev.w};
            #pragma unroll
            for (int i = 0; i < 4; i++)
                #pragma unroll
                for (int j = 0; j < 4; j++)
                    acc[i][j] = fmaf(a_[i], e_[j], acc[i][j]);
        }
        __syncthreads();
    }

    #pragma unroll
    for (int i = 0; i < 4; i++)
        #pragma unroll
        for (int j = 0; j < 4; j++)
            L[tb * 4 + i][te * 4 + j] = acc[i][j];
    __syncthreads();

    if (tid < 64) {
        int b = b0 + tid;
        float v[E_SZ];
        float mx = -1e30f;
        #pragma unroll
        for (int e = 0; e < E_SZ; e++) {
            float u = gu[(size_t)b * E_SZ + e];
            float g = -logf(-logf(u + 1e-10f) + 1e-10f);
            float t = L[tid][e] + b_att[e] + abias[e] + g;   // TAU = 1.0
            v[e] = t;
            mx = fmaxf(mx, t);
        }
        float s = 0.f;
        #pragma unroll
        for (int e = 0; e < E_SZ; e++) { v[e] = expf(v[e] - mx); s += v[e]; }
        float inv = 1.f / s;
        #pragma unroll
        for (int e = 0; e < E_SZ; e++) {
            float w = v[e] * inv;
            Wg[tid][e] = w;
            g_weights[(size_t)b * E_SZ + e] = w;
        }
    }
    __syncthreads();

    for (int idx = tid; idx < 64 * A_SZ; idx += 128) {
        int r = idx >> 7, a = idx & 127;
        float s = 0.f;
        #pragma unroll
        for (int e = 0; e < E_SZ; e++)
            s = fmaf(Wg[r][e], b_strat[e * A_SZ + a], s);
        out[(size_t)(b0 + r) * A_SZ + a] = s;
    }
}

// =====================================================================
// Main: fp16 m16n8k16. CTA 128x64, 512 threads, 16 warps as 2M x 8N.
// CTA-wide cp_w (R7 scheme, race-free) but amortized sync: W ring-8,
// prefetch distance 4, ONE __syncthreads + ONE wait_group per 4-tile
// group (128 barriers instead of 512). Reads (stages T..T+3) and
// writes (stages T+4..T+7) touch disjoint ring halves each group.
// =====================================================================
#define NTT   512                        // 16 P-chunks * 32 experts
#define WSB   16384                      // w_s: 32 e * 64 float2
#define XOFF  WSB
#define XBUF  16384                      // 2 mblocks * 8KB
#define WOFF  (XOFF + 2 * XBUF)          // 49152
#define WSTG  8192
#define SMEM_TOT (WOFF + 8 * WSTG)       // 114688

__global__ __launch_bounds__(512, 1) void main_kernel(float* __restrict__ out)
{
    extern __shared__ char smem[];
    float2* w_s = (float2*)smem;         // [e][64] row-pairs
    const uint32_t sb = smem_u32(smem);
    const int tid = threadIdx.x;
    const int lane = tid & 31, wid = tid >> 5;
    const int wm = wid >> 3, wn = wid & 7;        // 2M x 8N
    const int g = lane >> 2, tg = lane & 3;
    const int b0 = blockIdx.x * 128;
    const int a0 = blockIdx.y * 64;

    // gating weights, pre-paired: pair p=(wm,mt,g) -> rows (row, row+8)
    for (int i = tid; i < E_SZ * 64; i += 512) {
        int e = i >> 6, p = i & 63;
        int row = (p >> 5) * 64 + ((p >> 3) & 3) * 16 + (p & 7);
        float2 w2;
        w2.x = g_weights[(size_t)(b0 + row) * E_SZ + e];
        w2.y = g_weights[(size_t)(b0 + row + 8) * E_SZ + e];
        w_s[i] = w2;
    }

    auto cp_x = [&](int P) {
        uint32_t base = sb + XOFF + (P & 1) * XBUF;
        #pragma unroll
        for (int j = 0; j < 2; j++) {
            int f = tid + j * 512;                // 0..1023 16B-units
            int mb = f >> 9, rem = f & 511;
            const char* src = (const char*)g_xh +
                              ((size_t)((blockIdx.x * 2 + mb) * 16 + P)) * 8192 + rem * 16;
            cp16(base + f * 16, src);
        }
    };
    // CTA-wide: all 512 threads load 16B each of the 8KB tile (as R7)
    auto cp_w = [&](int t) {
        int P = t >> 5, e = t & 31;
        const char* src = (const char*)g_wh +
                          ((size_t)((e * 16 + P) * 16 + blockIdx.y * 8)) * 1024 + tid * 16;
        cp16(sb + WOFF + (t & 7) * WSTG + tid * 16, src);
    };

    // prologue: 4 groups, one per tile 0..3 (x rides with tile 0)
    cp_x(0); cp_w(0); CP_COMMIT();
    cp_w(1); CP_COMMIT();
    cp_w(2); CP_COMMIT();
    cp_w(3); CP_COMMIT();

    uint4 a_[2][2][4];                   // [dcsub][ks][mt]
    float master[4][4] = {};

    for (int T = 0; T < NTT; T += 4) {
        const int P = T >> 5;

        // prefetch next group's 4 tiles (one commit each; empty at tail ok)
        #pragma unroll
        for (int i = 0; i < 4; i++) {
            int tf = T + 4 + i;
            if (i == 0 && (T & 31) == 24 && P < 15) cp_x(P + 1);
            if (tf < NTT) cp_w(tf);
            CP_COMMIT();
        }
        CP_WAIT4();                      // groups for tiles <= T+3 complete
        __syncthreads();

        if ((T & 31) == 0) {             // chunk boundary: reload A frags
            const char* xb = smem + XOFF + (P & 1) * XBUF + wm * 8192;
            #pragma unroll
            for (int dcsub = 0; dcsub < 2; dcsub++)
                #pragma unroll
                for (int ks = 0; ks < 2; ks++)
                    #pragma unroll
                    for (int mt = 0; mt < 4; mt++) {
                        int fid = (dcsub * 2 + ks) * 4 + mt;
                        a_[dcsub][ks][mt] =
                            *(const uint4*)(xb + fid * 512 + lane * 16);
                    }
        }

        #pragma unroll
        for (int i = 0; i < 4; i++) {
            const int t = T + i, e = t & 31;
            const char* wb = smem + WOFF + (t & 7) * WSTG + wn * 1024;
            uint4 bfr0 = *(const uint4*)(wb + lane * 16);
            uint4 bfr1 = *(const uint4*)(wb + 512 + lane * 16);

            #pragma unroll
            for (int mt = 0; mt < 4; mt++) {
                float part[4];
                mma16z(part, a_[0][0][mt], bfr0.x, bfr0.y);
                mma16 (part, a_[0][1][mt], bfr0.z, bfr0.w);
                mma16 (part, a_[1][0][mt], bfr1.x, bfr1.y);
                mma16 (part, a_[1][1][mt], bfr1.z, bfr1.w);
                float2 w2 = w_s[e * 64 + wm * 32 + mt * 8 + g];
                master[mt][0] = fmaf(w2.x, part[0], master[mt][0]);
                master[mt][1] = fmaf(w2.x, part[1], master[mt][1]);
                master[mt][2] = fmaf(w2.y, part[2], master[mt][2]);
                master[mt][3] = fmaf(w2.y, part[3], master[mt][3]);
            }
        }
    }

    // epilogue: accumulate onto bias term already in out
    #pragma unroll
    for (int mt = 0; mt < 4; mt++) {
        int r = b0 + wm * 64 + mt * 16 + g;
        int c = a0 + wn * 8 + tg * 2;
        float2* p0 = (float2*)&out[(size_t)r * A_SZ + c];
        float2 v0 = *p0;
        v0.x += master[mt][0]; v0.y += master[mt][1];
        *p0 = v0;
        float2* p1 = (float2*)&out[(size_t)(r + 8) * A_SZ + c];
        float2 v1 = *p1;
        v1.x += master[mt][2]; v1.y += master[mt][3];
        *p1 = v1;
    }
}

// =====================================================================
extern "C" void kernel_launch(void* const* d_in, const int* in_sizes, int n_in,
                              void* d_out, int out_size) {
    const float* x       = (const float*)d_in[0];
    const float* W_att   = (const float*)d_in[1];
    const float* b_att   = (const float*)d_in[2];
    const float* abias   = (const float*)d_in[3];
    const float* W_strat = (const float*)d_in[4];
    const float* b_strat = (const float*)d_in[5];
    const float* gu      = (const float*)d_in[6];
    float* out = (float*)d_out;

    cudaFuncSetAttribute(main_kernel, cudaFuncAttributeMaxDynamicSharedMemorySize,
                         SMEM_TOT);

    convert_x_h<<<(B_SZ * D_SZ / 8) / 256, 256>>>(x);
    convert_w_h<<<(E_SZ * A_SZ * D_SZ / 8) / 256, 256>>>(W_strat);
    gating_kernel<<<B_SZ / 64, 128>>>(x, W_att, b_att, abias, b_strat, gu, out);
    main_kernel<<<dim3(B_SZ / 128, A_SZ / 64), 512, SMEM_TOT>>>(out);
}